// round 15
// baseline (speedup 1.0000x reference)
#include <cuda_runtime.h>
#include <cuda_fp16.h>
#include <math.h>
#include <stdint.h>

#define NUM_LAYERS 4
#define N_NODES 50000
#define N_PAD   50048            // 391 * 128
#define N_EDGES 800000
#define IN_FEAT 256
#define HIDDEN  512
#define MTILES  391

// ---------------- CSR scratch ----------------
__device__ int g_deg[N_NODES];
__device__ int g_row_ptr[N_NODES + 1];
__device__ int g_wptr[N_NODES];
__device__ int g_col[N_EDGES];

// ---------------- fp16 operand buffers ----------------
// Z-phase (inp @ Wi^T): SINGLE fp16 term -> only hi buffers.
// A-phase (aggr @ Wr^T): 3-term fp16 split -> hi + lo buffers.
__device__ __align__(16) __half g_xh[(size_t)N_PAD * IN_FEAT];
__device__ __align__(16) __half g_agh[(size_t)NUM_LAYERS * N_PAD * HIDDEN];
__device__ __align__(16) __half g_agl[(size_t)NUM_LAYERS * N_PAD * HIDDEN];
__device__ __align__(16) __half g_o1h[(size_t)N_PAD * HIDDEN];
__device__ __align__(16) __half g_o2h[(size_t)N_PAD * HIDDEN];
#define W1_ELEMS (131072 + 3 * 262144)
#define W2_ELEMS (4 * 262144)
__device__ __align__(16) __half g_w1h[W1_ELEMS];
__device__ __align__(16) __half g_w2h[W2_ELEMS];
__device__ __align__(16) __half g_w2l[W2_ELEMS];

// ---------------- helpers ----------------
__device__ __forceinline__ uint32_t smem_u32(const void* p) {
    uint32_t a;
    asm("{ .reg .u64 t; cvta.to.shared.u64 t, %1; cvt.u32.u64 %0, t; }"
        : "=r"(a) : "l"(p));
    return a;
}

__device__ __forceinline__ void cpa16(uint32_t dst, const void* src) {
    asm volatile("cp.async.cg.shared.global [%0], [%1], 16;"
                 :: "r"(dst), "l"(src) : "memory");
}
#define CP_COMMIT() asm volatile("cp.async.commit_group;" ::: "memory")
#define CP_WAIT(n)  asm volatile("cp.async.wait_group %0;" :: "n"(n) : "memory")

#define LDSM4(r0, r1, r2, r3, addr)                                            \
    asm volatile("ldmatrix.sync.aligned.m8n8.x4.shared.b16 {%0,%1,%2,%3}, [%4];" \
                 : "=r"(r0), "=r"(r1), "=r"(r2), "=r"(r3) : "r"(addr))

#define MMA16816(c, a0, a1, a2, a3, b0, b1)                                    \
    asm volatile("mma.sync.aligned.m16n8k16.row.col.f32.f16.f16.f32 "          \
                 "{%0,%1,%2,%3},{%4,%5,%6,%7},{%8,%9},{%0,%1,%2,%3};"          \
                 : "+f"((c)[0]), "+f"((c)[1]), "+f"((c)[2]), "+f"((c)[3])      \
                 : "r"(a0), "r"(a1), "r"(a2), "r"(a3), "r"(b0), "r"(b1))

__device__ __forceinline__ void split_f16(float v, __half& h, __half& l) {
    h = __float2half_rn(v);
    l = __float2half_rn(v - __half2float(h));
}

// fast tanh: 1 - 2/(e^{2x}+1); abs err ~1e-7
__device__ __forceinline__ float fast_tanh(float x) {
    float t = __expf(2.0f * x);
    return 1.0f - __fdividef(2.0f, t + 1.0f);
}

// ================= CSR build =================
__global__ void k_zero_deg() {
    for (int i = blockIdx.x * blockDim.x + threadIdx.x; i < N_NODES;
         i += gridDim.x * blockDim.x)
        g_deg[i] = 0;
}

__global__ void k_hist(const int* __restrict__ ei) {
    int e = blockIdx.x * blockDim.x + threadIdx.x;
    if (e < N_EDGES) {
        int dst = ei[N_EDGES + e];
        if ((unsigned)dst < (unsigned)N_NODES) atomicAdd(&g_deg[dst], 1);
    }
}

__global__ void k_scan() {
    __shared__ int buf[1024];
    int t = threadIdx.x;
    int carry = 0;
    for (int base = 0; base < N_NODES; base += 1024) {
        int i = base + t;
        int v = (i < N_NODES) ? g_deg[i] : 0;
        buf[t] = v;
        __syncthreads();
#pragma unroll
        for (int off = 1; off < 1024; off <<= 1) {
            int tmp = (t >= off) ? buf[t - off] : 0;
            __syncthreads();
            buf[t] += tmp;
            __syncthreads();
        }
        int incl = buf[t];
        if (i < N_NODES) {
            g_row_ptr[i + 1] = carry + incl;
            g_wptr[i]        = carry + incl - v;
        }
        carry += buf[1023];
        __syncthreads();
    }
    if (t == 0) g_row_ptr[0] = 0;
}

__global__ void k_scatter(const int* __restrict__ ei) {
    int e = blockIdx.x * blockDim.x + threadIdx.x;
    if (e < N_EDGES) {
        int src = ei[e];
        int dst = ei[N_EDGES + e];
        if ((unsigned)dst < (unsigned)N_NODES && (unsigned)src < (unsigned)N_NODES) {
            int pos = atomicAdd(&g_wptr[dst], 1);
            g_col[pos] = src;
        }
    }
}

// ================= conversions =================
__global__ void k_convert_x(const float* __restrict__ x) {
    const int groups = N_PAD * IN_FEAT / 4;
    for (int g = blockIdx.x * blockDim.x + threadIdx.x; g < groups;
         g += gridDim.x * blockDim.x) {
        int e = g * 4;
        int m = e / IN_FEAT;
        float4 v = make_float4(0.f, 0.f, 0.f, 0.f);
        if (m < N_NODES) v = *(const float4*)&x[e];
        *(__half2*)&g_xh[e]     = __floats2half2_rn(v.x, v.y);
        *(__half2*)&g_xh[e + 2] = __floats2half2_rn(v.z, v.w);
    }
}

__global__ void k_convert_w(const float* __restrict__ Wi0,
                            const float* __restrict__ Wi_rest,
                            const float* __restrict__ Wr) {
    // Wi: single fp16
    for (int g = blockIdx.x * blockDim.x + threadIdx.x; g < W1_ELEMS / 4;
         g += gridDim.x * blockDim.x) {
        int e = g * 4;
        float4 v = (e < 131072) ? *(const float4*)&Wi0[e]
                                : *(const float4*)&Wi_rest[e - 131072];
        *(__half2*)&g_w1h[e]     = __floats2half2_rn(v.x, v.y);
        *(__half2*)&g_w1h[e + 2] = __floats2half2_rn(v.z, v.w);
    }
    // Wr: fp16 hi/lo split
    for (int g = blockIdx.x * blockDim.x + threadIdx.x; g < W2_ELEMS / 4;
         g += gridDim.x * blockDim.x) {
        int e = g * 4;
        float4 v = *(const float4*)&Wr[e];
        __half h0, h1, h2, h3, l0, l1, l2, l3;
        split_f16(v.x, h0, l0); split_f16(v.y, h1, l1);
        split_f16(v.z, h2, l2); split_f16(v.w, h3, l3);
        *(__half2*)&g_w2h[e]     = __halves2half2(h0, h1);
        *(__half2*)&g_w2h[e + 2] = __halves2half2(h2, h3);
        *(__half2*)&g_w2l[e]     = __halves2half2(l0, l1);
        *(__half2*)&g_w2l[e + 2] = __halves2half2(l2, l3);
    }
}

// ================= aggregation: 256-thread / 2-node CTAs ====================
__global__ __launch_bounds__(256, 8)
void k_aggr(const float* __restrict__ states_layer,
            __half* __restrict__ agh,
            __half* __restrict__ agl)
{
    const int half_ = threadIdx.x >> 7;           // 0..1
    const int t     = threadIdx.x & 127;          // float4 column
    const int node  = blockIdx.x * 2 + half_;     // < N_PAD
    const float4* S = (const float4*)states_layer;

    float4 acc = make_float4(0.f, 0.f, 0.f, 0.f);
    if (node < N_NODES) {
        int e   = g_row_ptr[node];
        int end = g_row_ptr[node + 1];
        for (; e + 2 <= end; e += 2) {
            int s0 = g_col[e], s1 = g_col[e + 1];
            float4 v0 = S[(size_t)s0 * (HIDDEN / 4) + t];
            float4 v1 = S[(size_t)s1 * (HIDDEN / 4) + t];
            acc.x += v0.x + v1.x;
            acc.y += v0.y + v1.y;
            acc.z += v0.z + v1.z;
            acc.w += v0.w + v1.w;
        }
        if (e < end) {
            float4 v = S[(size_t)g_col[e] * (HIDDEN / 4) + t];
            acc.x += v.x; acc.y += v.y; acc.z += v.z; acc.w += v.w;
        }
    }
    size_t o = (size_t)node * HIDDEN + t * 4;
    __half h0, h1, h2, h3, l0, l1, l2, l3;
    split_f16(acc.x, h0, l0); split_f16(acc.y, h1, l1);
    split_f16(acc.z, h2, l2); split_f16(acc.w, h3, l3);
    *(__half2*)&agh[o]     = __halves2half2(h0, h1);
    *(__half2*)&agh[o + 2] = __halves2half2(h2, h3);
    *(__half2*)&agl[o]     = __halves2half2(l0, l1);
    *(__half2*)&agl[o + 2] = __halves2half2(l2, l3);
}

// ================= mma.sync dual-GEMM + tanh epilogue =================
// CTA tile 128x128x32; 8 warps 2(M)x4(N); warp tile 64x32.
// 2-stage cp.async double buffer = 81920 B SMEM => 2 CTAs/SM.
// Phase 1 (chunks < c1): SINGLE-term fp16 (hi only) -> 16 MMAs per ks.
// Phase 2 (chunks >= c1): 3-term fp16 split        -> 48 MMAs per ks.
#define ROWP 40
#define TE   (128 * ROWP)              // elems per tile = 5120
#define STAGE_E (4 * TE)               // elems per stage = 20480
#define SMEM_BYTES (2 * STAGE_E * 2)   // 81920 B

__device__ __forceinline__ void load_stage(
    uint32_t sbase,
    const __half* __restrict__ Ah, const __half* __restrict__ Al,
    const __half* __restrict__ Bh, const __half* __restrict__ Bl,
    int bm, int n0, int kof, int K, int tid, int full)
{
#pragma unroll
    for (int j = 0; j < 2; j++) {
        int idx = tid + j * 256;   // 0..511
        int r = idx >> 2;
        int c = idx & 3;
        uint32_t d = sbase + (uint32_t)(r * ROWP + c * 8) * 2;
        size_t ga = (size_t)(bm + r) * K + kof + c * 8;
        size_t gb = (size_t)(n0 + r) * K + kof + c * 8;
        cpa16(d,              Ah + ga);
        cpa16(d + 2 * TE * 2, Bh + gb);
        if (full) {
            cpa16(d + TE * 2,     Al + ga);
            cpa16(d + 3 * TE * 2, Bl + gb);
        }
    }
}

__global__ __launch_bounds__(296, 2)
void k_gemm_mma(const __half* __restrict__ a1h,
                const __half* __restrict__ b1h,
                const __half* __restrict__ a2h,
                const __half* __restrict__ a2l,
                const __half* __restrict__ b2h,
                const __half* __restrict__ b2l,
                int K1, int c1,
                const float* __restrict__ s_old,
                const float* __restrict__ leak,
                float* __restrict__ outp,
                __half* __restrict__ oh)
{
    extern __shared__ __half smem[];
    const uint32_t sm0 = smem_u32(smem);

    const int tid  = threadIdx.x;
    const int wid  = tid >> 5;
    const int lane = tid & 31;
    const int wm   = wid & 1;       // 0..1 (M)
    const int wn   = wid >> 1;      // 0..3 (N)
    const int bm   = blockIdx.y * 128;
    const int n0   = blockIdx.x * 128;

    float acc[4][4][4];
#pragma unroll
    for (int i = 0; i < 4; i++)
#pragma unroll
        for (int j = 0; j < 4; j++)
#pragma unroll
            for (int q = 0; q < 4; q++) acc[i][j][q] = 0.f;

    const int ctot = c1 + 16;

    // prologue: stage 0 = phase-1 chunk 0 (hi only)
    load_stage(sm0, a1h, nullptr, b1h, nullptr, bm, n0, 0, K1, tid, 0);
    CP_COMMIT();

    // ldmatrix lane-address components
    const int arow = (lane & 7) + ((lane >> 3) & 1) * 8;   // + wm*64 + mi*16
    const int acol = (lane >> 4) * 8;                       // + ks*16
    const int brow = (lane & 7) + (lane >> 4) * 8;          // + wn*32 + ng2*16
    const int bcol = ((lane >> 3) & 1) * 8;                 // + ks*16

    for (int ci = 0; ci < ctot; ci++) {
        if (ci + 1 < ctot) {
            int cj = ci + 1;
            uint32_t sb = sm0 + (uint32_t)((cj & 1) * STAGE_E) * 2;
            if (cj < c1)
                load_stage(sb, a1h, nullptr, b1h, nullptr, bm, n0,
                           cj * 32, K1, tid, 0);
            else
                load_stage(sb, a2h, a2l, b2h, b2l, bm, n0,
                           (cj - c1) * 32, HIDDEN, tid, 1);
            CP_COMMIT();
            CP_WAIT(1);
        } else {
            CP_WAIT(0);
        }
        __syncthreads();

        const int full = (ci >= c1);
        const uint32_t sb = sm0 + (uint32_t)((ci & 1) * STAGE_E) * 2;
        const uint32_t aB = sb + (uint32_t)((wm * 64 + arow) * ROWP + acol) * 2;
        const uint32_t bB = sb + (uint32_t)(2 * TE + (wn * 32 + brow) * ROWP + bcol) * 2;

#pragma unroll
        for (int ks = 0; ks < 2; ks++) {
            // af holds A-hi first; when full, it is later REUSED for A-lo.
            uint32_t af[4][4], bh[4][2], bl[4][2];
#pragma unroll
            for (int g2 = 0; g2 < 2; g2++) {
                uint32_t bd = bB + (uint32_t)(g2 * 16 * ROWP + ks * 16) * 2;
                uint32_t t0, t1, t2, t3;
                LDSM4(t0, t1, t2, t3, bd);
                bh[2 * g2][0] = t0; bh[2 * g2][1] = t1;
                bh[2 * g2 + 1][0] = t2; bh[2 * g2 + 1][1] = t3;
                if (full) {
                    LDSM4(t0, t1, t2, t3, bd + TE * 2);
                    bl[2 * g2][0] = t0; bl[2 * g2][1] = t1;
                    bl[2 * g2 + 1][0] = t2; bl[2 * g2 + 1][1] = t3;
                }
            }
#pragma unroll
            for (int mi = 0; mi < 4; mi++) {
                uint32_t ad = aB + (uint32_t)(mi * 16 * ROWP + ks * 16) * 2;
                LDSM4(af[mi][0], af[mi][1], af[mi][2], af[mi][3], ad);
            }
            // hh: Ah * Bh (always)
#pragma unroll
            for (int mi = 0; mi < 4; mi++)
#pragma unroll
                for (int ni = 0; ni < 4; ni++)
                    MMA16816(acc[mi][ni], af[mi][0], af[mi][1], af[mi][2], af[mi][3],
                             bh[ni][0], bh[ni][1]);
            if (full) {
                // hl: Ah * Bl
#pragma unroll
                for (int mi = 0; mi < 4; mi++)
#pragma unroll
                    for (int ni = 0; ni < 4; ni++)
                        MMA16816(acc[mi][ni], af[mi][0], af[mi][1], af[mi][2], af[mi][3],
                                 bl[ni][0], bl[ni][1]);
                // reload A-lo into af, then lh: Al * Bh
#pragma unroll
                for (int mi = 0; mi < 4; mi++) {
                    uint32_t ad = aB + (uint32_t)(mi * 16 * ROWP + ks * 16) * 2 + TE * 2;
                    LDSM4(af[mi][0], af[mi][1], af[mi][2], af[mi][3], ad);
                }
#pragma unroll
                for (int mi = 0; mi < 4; mi++)
#pragma unroll
                    for (int ni = 0; ni < 4; ni++)
                        MMA16816(acc[mi][ni], af[mi][0], af[mi][1], af[mi][2], af[mi][3],
                                 bh[ni][0], bh[ni][1]);
            }
        }
        __syncthreads();
    }

    // ---------------- epilogue ----------------
    const float a   = leak[0];
    const float oma = 1.0f - a;
#pragma unroll
    for (int mi = 0; mi < 4; mi++) {
#pragma unroll
        for (int h = 0; h < 2; h++) {
            int mm = bm + wm * 64 + mi * 16 + (lane >> 2) + h * 8;
            bool valid = (mm < N_NODES);
            size_t rowb = (size_t)mm * HIDDEN + n0 + wn * 32 + (lane & 3) * 2;
#pragma unroll
            for (int ni = 0; ni < 4; ni++) {
                size_t off = rowb + ni * 8;
                if (valid) {
                    float c0 = acc[mi][ni][2 * h];
                    float c1 = acc[mi][ni][2 * h + 1];
                    float2 s = *(const float2*)&s_old[off];
                    float o0 = a * fast_tanh(c0) + oma * s.x;
                    float o1 = a * fast_tanh(c1) + oma * s.y;
                    *(float2*)&outp[off] = make_float2(o0, o1);
                    if (oh)
                        *(__half2*)&oh[off] = __floats2half2_rn(o0, o1);
                } else if (oh) {
                    *(__half2*)&oh[off] = __floats2half2_rn(0.f, 0.f);
                }
            }
        }
    }
}

// ================= launch =================
extern "C" void kernel_launch(void* const* d_in, const int* in_sizes, int n_in,
                              void* d_out, int out_size)
{
    const int*   ei      = (const int*)d_in[0];       // [2, E] int32
    const float* x       = (const float*)d_in[1];     // [N, 256]
    const float* states  = (const float*)d_in[2];     // [4, N, 512]
    const float* Wi0     = (const float*)d_in[3];     // [512, 256]
    const float* Wi_rest = (const float*)d_in[4];     // [3, 512, 512]
    const float* Wr      = (const float*)d_in[5];     // [4, 512, 512]
    const float* leak    = (const float*)d_in[6];     // [1]
    float*       out     = (float*)d_out;             // [4, N, 512]

    (void)in_sizes; (void)n_in; (void)out_size;

    // one-time setup; ALL __device__ symbol addresses via cudaGetSymbolAddress
    static cudaStream_t sAg = nullptr;
    static cudaEvent_t evFork = nullptr;
    static cudaEvent_t evA[NUM_LAYERS];
    static __half *p_xh, *p_agh, *p_agl, *p_o1h, *p_o2h;
    static __half *p_w1h, *p_w2h, *p_w2l;
    if (sAg == nullptr) {
        cudaFuncSetAttribute(k_gemm_mma,
                             cudaFuncAttributeMaxDynamicSharedMemorySize,
                             SMEM_BYTES);
        cudaStreamCreateWithFlags(&sAg, cudaStreamNonBlocking);
        cudaEventCreateWithFlags(&evFork, cudaEventDisableTiming);
        for (int l = 0; l < NUM_LAYERS; l++)
            cudaEventCreateWithFlags(&evA[l], cudaEventDisableTiming);
        cudaGetSymbolAddress((void**)&p_xh,  g_xh);
        cudaGetSymbolAddress((void**)&p_agh, g_agh);
        cudaGetSymbolAddress((void**)&p_agl, g_agl);
        cudaGetSymbolAddress((void**)&p_o1h, g_o1h);
        cudaGetSymbolAddress((void**)&p_o2h, g_o2h);
        cudaGetSymbolAddress((void**)&p_w1h, g_w1h);
        cudaGetSymbolAddress((void**)&p_w2h, g_w2h);
        cudaGetSymbolAddress((void**)&p_w2l, g_w2l);
    }

    // ---- main stream: CSR build ----
    k_zero_deg<<<128, 256>>>();
    k_hist<<<(N_EDGES + 255) / 256, 256>>>(ei);
    k_scan<<<1, 1024>>>();
    k_scatter<<<(N_EDGES + 255) / 256, 256>>>(ei);

    // ---- legal capture fork (event recorded on origin stream) ----
    cudaEventRecord(evFork, 0);
    cudaStreamWaitEvent(sAg, evFork, 0);

    // ---- side stream: 4 layer aggregations ----
    for (int l = 0; l < NUM_LAYERS; l++) {
        size_t off = (size_t)l * N_PAD * HIDDEN;
        k_aggr<<<N_PAD / 2, 256, 0, sAg>>>(states + (size_t)l * N_NODES * HIDDEN,
                                           p_agh + off, p_agl + off);
        cudaEventRecord(evA[l], sAg);
    }

    // ---- main stream: conversions (overlap with aggr0) ----
    k_convert_x<<<4096, 256>>>(x);
    k_convert_w<<<1024, 256>>>(Wi0, Wi_rest, Wr);

    // ---- main stream: sequential GEMM chain; GEMM l waits on aggr l ----
    const __half* a1h[4] = {p_xh, p_o1h, p_o2h, p_o1h};
    __half* ohv[4] = {p_o1h, p_o2h, p_o1h, nullptr};
    dim3 grid(HIDDEN / 128, MTILES);
    for (int l = 0; l < NUM_LAYERS; l++) {
        int K1 = (l == 0) ? IN_FEAT : HIDDEN;
        int c1 = K1 / 32;
        const size_t w1off = (l == 0) ? 0 : (size_t)131072 + (size_t)(l - 1) * 262144;
        const size_t aoff  = (size_t)l * N_PAD * HIDDEN;
        cudaStreamWaitEvent(0, evA[l], 0);
        k_gemm_mma<<<grid, 256, SMEM_BYTES>>>(
            a1h[l], p_w1h + w1off,
            p_agh + aoff, p_agl + aoff,
            p_w2h + (size_t)l * 262144, p_w2l + (size_t)l * 262144,
            K1, c1,
            states + (size_t)l * N_NODES * HIDDEN, leak,
            out + (size_t)l * N_NODES * HIDDEN, ohv[l]);
    }
}

// round 16
// speedup vs baseline: 1.4125x; 1.4125x over previous
#include <cuda_runtime.h>
#include <cuda_fp16.h>
#include <cuda_bf16.h>
#include <math.h>
#include <stdint.h>

#define NUM_LAYERS 4
#define N_NODES 50000
#define N_PAD   50048            // 391 * 128
#define N_EDGES 800000
#define IN_FEAT 256
#define HIDDEN  512
#define MTILES  391

// ---------------- CSR scratch ----------------
__device__ int g_deg[N_NODES];
__device__ int g_row_ptr[N_NODES + 1];
__device__ int g_wptr[N_NODES];
__device__ int g_col[N_EDGES];

// ---------------- operand buffers ----------------
// Z-phase (inp @ Wi^T): SINGLE-term fp16 (validated rel_err ~1e-4).
// A-phase (aggr @ Wr^T): 3-term bf16 split (champion path, proven rate).
__device__ __align__(16) __half         g_xh[(size_t)N_PAD * IN_FEAT];
__device__ __align__(16) __half         g_o1h[(size_t)N_PAD * HIDDEN];
__device__ __align__(16) __half         g_o2h[(size_t)N_PAD * HIDDEN];
__device__ __align__(16) __nv_bfloat16 g_agh[(size_t)NUM_LAYERS * N_PAD * HIDDEN];
__device__ __align__(16) __nv_bfloat16 g_agl[(size_t)NUM_LAYERS * N_PAD * HIDDEN];
#define W1_ELEMS (131072 + 3 * 262144)
#define W2_ELEMS (4 * 262144)
__device__ __align__(16) __half         g_w1h[W1_ELEMS];
__device__ __align__(16) __nv_bfloat16 g_w2h[W2_ELEMS];
__device__ __align__(16) __nv_bfloat16 g_w2l[W2_ELEMS];

// ---------------- helpers ----------------
__device__ __forceinline__ uint32_t smem_u32(const void* p) {
    uint32_t a;
    asm("{ .reg .u64 t; cvta.to.shared.u64 t, %1; cvt.u32.u64 %0, t; }"
        : "=r"(a) : "l"(p));
    return a;
}

__device__ __forceinline__ void cpa16(uint32_t dst, const void* src) {
    asm volatile("cp.async.cg.shared.global [%0], [%1], 16;"
                 :: "r"(dst), "l"(src) : "memory");
}
#define CP_COMMIT() asm volatile("cp.async.commit_group;" ::: "memory")
#define CP_WAIT(n)  asm volatile("cp.async.wait_group %0;" :: "n"(n) : "memory")

#define LDSM4(r0, r1, r2, r3, addr)                                            \
    asm volatile("ldmatrix.sync.aligned.m8n8.x4.shared.b16 {%0,%1,%2,%3}, [%4];" \
                 : "=r"(r0), "=r"(r1), "=r"(r2), "=r"(r3) : "r"(addr))

#define MMA_BF16(c, a0, a1, a2, a3, b0, b1)                                    \
    asm volatile("mma.sync.aligned.m16n8k16.row.col.f32.bf16.bf16.f32 "        \
                 "{%0,%1,%2,%3},{%4,%5,%6,%7},{%8,%9},{%0,%1,%2,%3};"          \
                 : "+f"((c)[0]), "+f"((c)[1]), "+f"((c)[2]), "+f"((c)[3])      \
                 : "r"(a0), "r"(a1), "r"(a2), "r"(a3), "r"(b0), "r"(b1))

#define MMA_F16(c, a0, a1, a2, a3, b0, b1)                                     \
    asm volatile("mma.sync.aligned.m16n8k16.row.col.f32.f16.f16.f32 "          \
                 "{%0,%1,%2,%3},{%4,%5,%6,%7},{%8,%9},{%0,%1,%2,%3};"          \
                 : "+f"((c)[0]), "+f"((c)[1]), "+f"((c)[2]), "+f"((c)[3])      \
                 : "r"(a0), "r"(a1), "r"(a2), "r"(a3), "r"(b0), "r"(b1))

__device__ __forceinline__ void split_bf16(float v, __nv_bfloat16& h, __nv_bfloat16& l) {
    h = __float2bfloat16_rn(v);
    l = __float2bfloat16_rn(v - __bfloat162float(h));
}

// fast tanh: 1 - 2/(e^{2x}+1); abs err ~1e-7
__device__ __forceinline__ float fast_tanh(float x) {
    float t = __expf(2.0f * x);
    return 1.0f - __fdividef(2.0f, t + 1.0f);
}

// ================= CSR build =================
__global__ void k_zero_deg() {
    for (int i = blockIdx.x * blockDim.x + threadIdx.x; i < N_NODES;
         i += gridDim.x * blockDim.x)
        g_deg[i] = 0;
}

__global__ void k_hist(const int* __restrict__ ei) {
    int e = blockIdx.x * blockDim.x + threadIdx.x;
    if (e < N_EDGES) {
        int dst = ei[N_EDGES + e];
        if ((unsigned)dst < (unsigned)N_NODES) atomicAdd(&g_deg[dst], 1);
    }
}

__global__ void k_scan() {
    __shared__ int buf[1024];
    int t = threadIdx.x;
    int carry = 0;
    for (int base = 0; base < N_NODES; base += 1024) {
        int i = base + t;
        int v = (i < N_NODES) ? g_deg[i] : 0;
        buf[t] = v;
        __syncthreads();
#pragma unroll
        for (int off = 1; off < 1024; off <<= 1) {
            int tmp = (t >= off) ? buf[t - off] : 0;
            __syncthreads();
            buf[t] += tmp;
            __syncthreads();
        }
        int incl = buf[t];
        if (i < N_NODES) {
            g_row_ptr[i + 1] = carry + incl;
            g_wptr[i]        = carry + incl - v;
        }
        carry += buf[1023];
        __syncthreads();
    }
    if (t == 0) g_row_ptr[0] = 0;
}

__global__ void k_scatter(const int* __restrict__ ei) {
    int e = blockIdx.x * blockDim.x + threadIdx.x;
    if (e < N_EDGES) {
        int src = ei[e];
        int dst = ei[N_EDGES + e];
        if ((unsigned)dst < (unsigned)N_NODES && (unsigned)src < (unsigned)N_NODES) {
            int pos = atomicAdd(&g_wptr[dst], 1);
            g_col[pos] = src;
        }
    }
}

// ================= conversions =================
__global__ void k_convert_x(const float* __restrict__ x) {
    const int groups = N_PAD * IN_FEAT / 4;
    for (int g = blockIdx.x * blockDim.x + threadIdx.x; g < groups;
         g += gridDim.x * blockDim.x) {
        int e = g * 4;
        int m = e / IN_FEAT;
        float4 v = make_float4(0.f, 0.f, 0.f, 0.f);
        if (m < N_NODES) v = *(const float4*)&x[e];
        *(__half2*)&g_xh[e]     = __floats2half2_rn(v.x, v.y);
        *(__half2*)&g_xh[e + 2] = __floats2half2_rn(v.z, v.w);
    }
}

__global__ void k_convert_w(const float* __restrict__ Wi0,
                            const float* __restrict__ Wi_rest,
                            const float* __restrict__ Wr) {
    // Wi: plain fp16
    for (int g = blockIdx.x * blockDim.x + threadIdx.x; g < W1_ELEMS / 4;
         g += gridDim.x * blockDim.x) {
        int e = g * 4;
        float4 v = (e < 131072) ? *(const float4*)&Wi0[e]
                                : *(const float4*)&Wi_rest[e - 131072];
        *(__half2*)&g_w1h[e]     = __floats2half2_rn(v.x, v.y);
        *(__half2*)&g_w1h[e + 2] = __floats2half2_rn(v.z, v.w);
    }
    // Wr: bf16 hi/lo split
    for (int g = blockIdx.x * blockDim.x + threadIdx.x; g < W2_ELEMS / 4;
         g += gridDim.x * blockDim.x) {
        int e = g * 4;
        float4 v = *(const float4*)&Wr[e];
        __nv_bfloat16 h0, h1, h2, h3, l0, l1, l2, l3;
        split_bf16(v.x, h0, l0); split_bf16(v.y, h1, l1);
        split_bf16(v.z, h2, l2); split_bf16(v.w, h3, l3);
        *(__nv_bfloat162*)&g_w2h[e]     = __halves2bfloat162(h0, h1);
        *(__nv_bfloat162*)&g_w2h[e + 2] = __halves2bfloat162(h2, h3);
        *(__nv_bfloat162*)&g_w2l[e]     = __halves2bfloat162(l0, l1);
        *(__nv_bfloat162*)&g_w2l[e + 2] = __halves2bfloat162(l2, l3);
    }
}

// ================= aggregation: 256-thread / 2-node CTAs (bf16 split out) ===
__global__ __launch_bounds__(256, 8)
void k_aggr(const float* __restrict__ states_layer,
            __nv_bfloat16* __restrict__ agh,
            __nv_bfloat16* __restrict__ agl)
{
    const int half_ = threadIdx.x >> 7;           // 0..1
    const int t     = threadIdx.x & 127;          // float4 column
    const int node  = blockIdx.x * 2 + half_;     // < N_PAD
    const float4* S = (const float4*)states_layer;

    float4 acc = make_float4(0.f, 0.f, 0.f, 0.f);
    if (node < N_NODES) {
        int e   = g_row_ptr[node];
        int end = g_row_ptr[node + 1];
        for (; e + 2 <= end; e += 2) {
            int s0 = g_col[e], s1 = g_col[e + 1];
            float4 v0 = S[(size_t)s0 * (HIDDEN / 4) + t];
            float4 v1 = S[(size_t)s1 * (HIDDEN / 4) + t];
            acc.x += v0.x + v1.x;
            acc.y += v0.y + v1.y;
            acc.z += v0.z + v1.z;
            acc.w += v0.w + v1.w;
        }
        if (e < end) {
            float4 v = S[(size_t)g_col[e] * (HIDDEN / 4) + t];
            acc.x += v.x; acc.y += v.y; acc.z += v.z; acc.w += v.w;
        }
    }
    size_t o = (size_t)node * HIDDEN + t * 4;
    __nv_bfloat16 h0, h1, h2, h3, l0, l1, l2, l3;
    split_bf16(acc.x, h0, l0); split_bf16(acc.y, h1, l1);
    split_bf16(acc.z, h2, l2); split_bf16(acc.w, h3, l3);
    *(__nv_bfloat162*)&agh[o]     = __halves2bfloat162(h0, h1);
    *(__nv_bfloat162*)&agh[o + 2] = __halves2bfloat162(h2, h3);
    *(__nv_bfloat162*)&agl[o]     = __halves2bfloat162(l0, l1);
    *(__nv_bfloat162*)&agl[o + 2] = __halves2bfloat162(l2, l3);
}

// ================= mixed-precision dual-GEMM + tanh epilogue ===============
// CTA tile 128x128x32; 8 warps 2(M)x4(N); warp tile 64x32.
// 2-stage cp.async double buffer = 81920 B SMEM => 2 CTAs/SM.
// TWO SEPARATE MAINLOOPS (branch-free bodies):
//   loop 1 (c1 chunks):  fp16 single-term  -> 16 MMAs per ks
//   loop 2 (16 chunks):  bf16 3-term split -> 48 MMAs per ks
#define ROWP 40
#define TE   (128 * ROWP)              // elems per tile = 5120
#define STAGE_E (4 * TE)               // elems per stage = 20480
#define SMEM_BYTES (2 * STAGE_E * 2)   // 81920 B

__device__ __forceinline__ void load_stage_light(
    uint32_t sbase, const __half* __restrict__ Ah,
    const __half* __restrict__ Bh,
    int bm, int n0, int kof, int K, int tid)
{
#pragma unroll
    for (int j = 0; j < 2; j++) {
        int idx = tid + j * 256;
        int r = idx >> 2;
        int c = idx & 3;
        uint32_t d = sbase + (uint32_t)(r * ROWP + c * 8) * 2;
        cpa16(d,              Ah + (size_t)(bm + r) * K + kof + c * 8);
        cpa16(d + 2 * TE * 2, Bh + (size_t)(n0 + r) * K + kof + c * 8);
    }
}

__device__ __forceinline__ void load_stage_full(
    uint32_t sbase,
    const __nv_bfloat16* __restrict__ Ah, const __nv_bfloat16* __restrict__ Al,
    const __nv_bfloat16* __restrict__ Bh, const __nv_bfloat16* __restrict__ Bl,
    int bm, int n0, int kof, int tid)
{
#pragma unroll
    for (int j = 0; j < 2; j++) {
        int idx = tid + j * 256;
        int r = idx >> 2;
        int c = idx & 3;
        uint32_t d = sbase + (uint32_t)(r * ROWP + c * 8) * 2;
        size_t ga = (size_t)(bm + r) * HIDDEN + kof + c * 8;
        size_t gb = (size_t)(n0 + r) * HIDDEN + kof + c * 8;
        cpa16(d,              Ah + ga);
        cpa16(d + TE * 2,     Al + ga);
        cpa16(d + 2 * TE * 2, Bh + gb);
        cpa16(d + 3 * TE * 2, Bl + gb);
    }
}

// fp16 single-term compute for one chunk (both ks halves)
__device__ __forceinline__ void compute_light(
    uint32_t sb, float acc[4][4][4],
    int wm, int wn, int arow, int acol, int brow, int bcol)
{
#pragma unroll
    for (int ks = 0; ks < 2; ks++) {
        const uint32_t aB = sb + (uint32_t)((wm * 64 + arow) * ROWP + acol + ks * 16) * 2;
        const uint32_t bB = sb + (uint32_t)(2 * TE + (wn * 32 + brow) * ROWP + bcol + ks * 16) * 2;
        uint32_t af[4][4], bh[4][2];
#pragma unroll
        for (int g2 = 0; g2 < 2; g2++) {
            uint32_t t0, t1, t2, t3;
            LDSM4(t0, t1, t2, t3, bB + (uint32_t)(g2 * 16 * ROWP) * 2);
            bh[2 * g2][0] = t0; bh[2 * g2][1] = t1;
            bh[2 * g2 + 1][0] = t2; bh[2 * g2 + 1][1] = t3;
        }
#pragma unroll
        for (int mi = 0; mi < 4; mi++)
            LDSM4(af[mi][0], af[mi][1], af[mi][2], af[mi][3],
                  aB + (uint32_t)(mi * 16 * ROWP) * 2);
#pragma unroll
        for (int mi = 0; mi < 4; mi++)
#pragma unroll
            for (int ni = 0; ni < 4; ni++)
                MMA_F16(acc[mi][ni], af[mi][0], af[mi][1], af[mi][2], af[mi][3],
                        bh[ni][0], bh[ni][1]);
    }
}

// bf16 3-term compute for one chunk (both ks halves)
__device__ __forceinline__ void compute_full(
    uint32_t sb, float acc[4][4][4],
    int wm, int wn, int arow, int acol, int brow, int bcol)
{
#pragma unroll
    for (int ks = 0; ks < 2; ks++) {
        const uint32_t aB = sb + (uint32_t)((wm * 64 + arow) * ROWP + acol + ks * 16) * 2;
        const uint32_t bB = sb + (uint32_t)(2 * TE + (wn * 32 + brow) * ROWP + bcol + ks * 16) * 2;
        uint32_t af[4][4], bh[4][2], bl[4][2];
#pragma unroll
        for (int g2 = 0; g2 < 2; g2++) {
            uint32_t bd = bB + (uint32_t)(g2 * 16 * ROWP) * 2;
            uint32_t t0, t1, t2, t3;
            LDSM4(t0, t1, t2, t3, bd);
            bh[2 * g2][0] = t0; bh[2 * g2][1] = t1;
            bh[2 * g2 + 1][0] = t2; bh[2 * g2 + 1][1] = t3;
            LDSM4(t0, t1, t2, t3, bd + TE * 2);
            bl[2 * g2][0] = t0; bl[2 * g2][1] = t1;
            bl[2 * g2 + 1][0] = t2; bl[2 * g2 + 1][1] = t3;
        }
#pragma unroll
        for (int mi = 0; mi < 4; mi++)
            LDSM4(af[mi][0], af[mi][1], af[mi][2], af[mi][3],
                  aB + (uint32_t)(mi * 16 * ROWP) * 2);
        // hh
#pragma unroll
        for (int mi = 0; mi < 4; mi++)
#pragma unroll
            for (int ni = 0; ni < 4; ni++)
                MMA_BF16(acc[mi][ni], af[mi][0], af[mi][1], af[mi][2], af[mi][3],
                         bh[ni][0], bh[ni][1]);
        // hl
#pragma unroll
        for (int mi = 0; mi < 4; mi++)
#pragma unroll
            for (int ni = 0; ni < 4; ni++)
                MMA_BF16(acc[mi][ni], af[mi][0], af[mi][1], af[mi][2], af[mi][3],
                         bl[ni][0], bl[ni][1]);
        // reload A-lo, then lh
#pragma unroll
        for (int mi = 0; mi < 4; mi++)
            LDSM4(af[mi][0], af[mi][1], af[mi][2], af[mi][3],
                  aB + (uint32_t)(mi * 16 * ROWP) * 2 + TE * 2);
#pragma unroll
        for (int mi = 0; mi < 4; mi++)
#pragma unroll
            for (int ni = 0; ni < 4; ni++)
                MMA_BF16(acc[mi][ni], af[mi][0], af[mi][1], af[mi][2], af[mi][3],
                         bh[ni][0], bh[ni][1]);
    }
}

__global__ __launch_bounds__(296, 2)
void k_gemm_mma(const __half* __restrict__ a1h,
                const __half* __restrict__ b1h,
                const __nv_bfloat16* __restrict__ a2h,
                const __nv_bfloat16* __restrict__ a2l,
                const __nv_bfloat16* __restrict__ b2h,
                const __nv_bfloat16* __restrict__ b2l,
                int K1, int c1,
                const float* __restrict__ s_old,
                const float* __restrict__ leak,
                float* __restrict__ outp,
                __half* __restrict__ oh)
{
    extern __shared__ __half smem[];
    const uint32_t sm0 = smem_u32(smem);

    const int tid  = threadIdx.x;
    const int wid  = tid >> 5;
    const int lane = tid & 31;
    const int wm   = wid & 1;       // 0..1 (M)
    const int wn   = wid >> 1;      // 0..3 (N)
    const int bm   = blockIdx.y * 128;
    const int n0   = blockIdx.x * 128;

    float acc[4][4][4];
#pragma unroll
    for (int i = 0; i < 4; i++)
#pragma unroll
        for (int j = 0; j < 4; j++)
#pragma unroll
            for (int q = 0; q < 4; q++) acc[i][j][q] = 0.f;

    // ldmatrix lane-address components
    const int arow = (lane & 7) + ((lane >> 3) & 1) * 8;
    const int acol = (lane >> 4) * 8;
    const int brow = (lane & 7) + (lane >> 4) * 8;
    const int bcol = ((lane >> 3) & 1) * 8;

    // prologue: chunk 0 (phase 1)
    load_stage_light(sm0, a1h, b1h, bm, n0, 0, K1, tid);
    CP_COMMIT();

    int stage = 0;
    // ---- loop 1: fp16 single-term (chunks 0..c1-1) ----
    for (int ci = 0; ci < c1; ci++) {
        uint32_t nsb = sm0 + (uint32_t)((stage ^ 1) * STAGE_E) * 2;
        if (ci + 1 < c1)
            load_stage_light(nsb, a1h, b1h, bm, n0, (ci + 1) * 32, K1, tid);
        else
            load_stage_full(nsb, a2h, a2l, b2h, b2l, bm, n0, 0, tid);
        CP_COMMIT();
        CP_WAIT(1);
        __syncthreads();
        compute_light(sm0 + (uint32_t)(stage * STAGE_E) * 2, acc,
                      wm, wn, arow, acol, brow, bcol);
        __syncthreads();
        stage ^= 1;
    }
    // ---- loop 2: bf16 3-term (16 chunks) ----
    for (int cj = 0; cj < 16; cj++) {
        if (cj + 1 < 16) {
            uint32_t nsb = sm0 + (uint32_t)((stage ^ 1) * STAGE_E) * 2;
            load_stage_full(nsb, a2h, a2l, b2h, b2l, bm, n0, (cj + 1) * 32, tid);
            CP_COMMIT();
            CP_WAIT(1);
        } else {
            CP_WAIT(0);
        }
        __syncthreads();
        compute_full(sm0 + (uint32_t)(stage * STAGE_E) * 2, acc,
                     wm, wn, arow, acol, brow, bcol);
        __syncthreads();
        stage ^= 1;
    }

    // ---------------- epilogue ----------------
    const float a   = leak[0];
    const float oma = 1.0f - a;
#pragma unroll
    for (int mi = 0; mi < 4; mi++) {
#pragma unroll
        for (int h = 0; h < 2; h++) {
            int mm = bm + wm * 64 + mi * 16 + (lane >> 2) + h * 8;
            bool valid = (mm < N_NODES);
            size_t rowb = (size_t)mm * HIDDEN + n0 + wn * 32 + (lane & 3) * 2;
#pragma unroll
            for (int ni = 0; ni < 4; ni++) {
                size_t off = rowb + ni * 8;
                if (valid) {
                    float c0 = acc[mi][ni][2 * h];
                    float c1 = acc[mi][ni][2 * h + 1];
                    float2 s = *(const float2*)&s_old[off];
                    float o0 = a * fast_tanh(c0) + oma * s.x;
                    float o1 = a * fast_tanh(c1) + oma * s.y;
                    *(float2*)&outp[off] = make_float2(o0, o1);
                    if (oh)
                        *(__half2*)&oh[off] = __floats2half2_rn(o0, o1);
                } else if (oh) {
                    *(__half2*)&oh[off] = __floats2half2_rn(0.f, 0.f);
                }
            }
        }
    }
}

// ================= launch =================
extern "C" void kernel_launch(void* const* d_in, const int* in_sizes, int n_in,
                              void* d_out, int out_size)
{
    const int*   ei      = (const int*)d_in[0];       // [2, E] int32
    const float* x       = (const float*)d_in[1];     // [N, 256]
    const float* states  = (const float*)d_in[2];     // [4, N, 512]
    const float* Wi0     = (const float*)d_in[3];     // [512, 256]
    const float* Wi_rest = (const float*)d_in[4];     // [3, 512, 512]
    const float* Wr      = (const float*)d_in[5];     // [4, 512, 512]
    const float* leak    = (const float*)d_in[6];     // [1]
    float*       out     = (float*)d_out;             // [4, N, 512]

    (void)in_sizes; (void)n_in; (void)out_size;

    // one-time setup; ALL __device__ symbol addresses via cudaGetSymbolAddress
    static cudaStream_t sAg = nullptr;
    static cudaEvent_t evFork = nullptr;
    static cudaEvent_t evA[NUM_LAYERS];
    static __half *p_xh, *p_o1h, *p_o2h, *p_w1h;
    static __nv_bfloat16 *p_agh, *p_agl, *p_w2h, *p_w2l;
    if (sAg == nullptr) {
        cudaFuncSetAttribute(k_gemm_mma,
                             cudaFuncAttributeMaxDynamicSharedMemorySize,
                             SMEM_BYTES);
        cudaStreamCreateWithFlags(&sAg, cudaStreamNonBlocking);
        cudaEventCreateWithFlags(&evFork, cudaEventDisableTiming);
        for (int l = 0; l < NUM_LAYERS; l++)
            cudaEventCreateWithFlags(&evA[l], cudaEventDisableTiming);
        cudaGetSymbolAddress((void**)&p_xh,  g_xh);
        cudaGetSymbolAddress((void**)&p_o1h, g_o1h);
        cudaGetSymbolAddress((void**)&p_o2h, g_o2h);
        cudaGetSymbolAddress((void**)&p_w1h, g_w1h);
        cudaGetSymbolAddress((void**)&p_agh, g_agh);
        cudaGetSymbolAddress((void**)&p_agl, g_agl);
        cudaGetSymbolAddress((void**)&p_w2h, g_w2h);
        cudaGetSymbolAddress((void**)&p_w2l, g_w2l);
    }

    // ---- main stream: CSR build ----
    k_zero_deg<<<128, 256>>>();
    k_hist<<<(N_EDGES + 255) / 256, 256>>>(ei);
    k_scan<<<1, 1024>>>();
    k_scatter<<<(N_EDGES + 255) / 256, 256>>>(ei);

    // ---- legal capture fork (event recorded on origin stream) ----
    cudaEventRecord(evFork, 0);
    cudaStreamWaitEvent(sAg, evFork, 0);

    // ---- side stream: 4 layer aggregations ----
    for (int l = 0; l < NUM_LAYERS; l++) {
        size_t off = (size_t)l * N_PAD * HIDDEN;
        k_aggr<<<N_PAD / 2, 256, 0, sAg>>>(states + (size_t)l * N_NODES * HIDDEN,
                                           p_agh + off, p_agl + off);
        cudaEventRecord(evA[l], sAg);
    }

    // ---- main stream: conversions (overlap with aggr0) ----
    k_convert_x<<<4096, 256>>>(x);
    k_convert_w<<<1024, 256>>>(Wi0, Wi_rest, Wr);

    // ---- main stream: sequential GEMM chain; GEMM l waits on aggr l ----
    const __half* a1h[4] = {p_xh, p_o1h, p_o2h, p_o1h};
    __half* ohv[4] = {p_o1h, p_o2h, p_o1h, nullptr};
    dim3 grid(HIDDEN / 128, MTILES);
    for (int l = 0; l < NUM_LAYERS; l++) {
        int K1 = (l == 0) ? IN_FEAT : HIDDEN;
        int c1 = K1 / 32;
        const size_t w1off = (l == 0) ? 0 : (size_t)131072 + (size_t)(l - 1) * 262144;
        const size_t aoff  = (size_t)l * N_PAD * HIDDEN;
        cudaStreamWaitEvent(0, evA[l], 0);
        k_gemm_mma<<<grid, 256, SMEM_BYTES>>>(
            a1h[l], p_w1h + w1off,
            p_agh + aoff, p_agl + aoff,
            p_w2h + (size_t)l * 262144, p_w2l + (size_t)l * 262144,
            K1, c1,
            states + (size_t)l * N_NODES * HIDDEN, leak,
            out + (size_t)l * N_NODES * HIDDEN, ohv[l]);
    }
}